// round 3
// baseline (speedup 1.0000x reference)
#include <cuda_runtime.h>

#define B_   32
#define T_   512
#define D_   512
#define H_   8
#define DK_  64
#define M_   (B_ * T_)   // 16384

// ---- scratch (no allocations allowed) ----
__device__ float g_q[M_ * D_];
__device__ float g_k[M_ * D_];
__device__ float g_v[M_ * D_];
__device__ float g_att[M_ * D_];

// ============================================================================
// C[M,N] = A[M,K] @ W[N,K]^T + bias[N]      (both operands K-contiguous: "NT")
// 64x64 block tile, BK=16, 256 threads, 4x4 per-thread tile.
// Smem tiles stored transposed [BK][BM] so compute reads are contiguous float4.
// ============================================================================
__global__ __launch_bounds__(256) void sgemm_nt_bias(
    const float* __restrict__ A, const float* __restrict__ W,
    const float* __restrict__ bias, float* __restrict__ C,
    int M, int N, int K)
{
    __shared__ float As[16][68];   // [kk][row], pad 68 -> 16B-aligned rows, fewer store conflicts
    __shared__ float Bs[16][68];   // [kk][col]

    const int m0  = blockIdx.y * 64;
    const int n0  = blockIdx.x * 64;
    const int tid = threadIdx.x;
    const int ty  = tid >> 4;          // 0..15 -> rows ty*4..ty*4+3
    const int tx  = tid & 15;          // 0..15 -> cols tx*4..tx*4+3
    const int lr  = tid >> 2;          // load row 0..63
    const int lc  = (tid & 3) << 2;    // load col chunk {0,4,8,12}

    const float* Ap = A + (size_t)(m0 + lr) * K + lc;
    const float* Wp = W + (size_t)(n0 + lr) * K + lc;

    float acc[4][4] = {};

    for (int k0 = 0; k0 < K; k0 += 16) {
        float4 av = *(const float4*)(Ap + k0);
        float4 bv = *(const float4*)(Wp + k0);
        As[lc + 0][lr] = av.x; As[lc + 1][lr] = av.y;
        As[lc + 2][lr] = av.z; As[lc + 3][lr] = av.w;
        Bs[lc + 0][lr] = bv.x; Bs[lc + 1][lr] = bv.y;
        Bs[lc + 2][lr] = bv.z; Bs[lc + 3][lr] = bv.w;
        __syncthreads();

        #pragma unroll
        for (int kk = 0; kk < 16; kk++) {
            float4 a4 = *(const float4*)&As[kk][ty * 4];
            float4 b4 = *(const float4*)&Bs[kk][tx * 4];
            float a[4] = {a4.x, a4.y, a4.z, a4.w};
            float b[4] = {b4.x, b4.y, b4.z, b4.w};
            #pragma unroll
            for (int i = 0; i < 4; i++)
                #pragma unroll
                for (int j = 0; j < 4; j++)
                    acc[i][j] = fmaf(a[i], b[j], acc[i][j]);
        }
        __syncthreads();
    }

    float4 bb = *(const float4*)(bias + n0 + tx * 4);
    float bj[4] = {bb.x, bb.y, bb.z, bb.w};
    #pragma unroll
    for (int i = 0; i < 4; i++) {
        float4 o;
        o.x = acc[i][0] + bj[0]; o.y = acc[i][1] + bj[1];
        o.z = acc[i][2] + bj[2]; o.w = acc[i][3] + bj[3];
        *(float4*)(C + (size_t)(m0 + ty * 4 + i) * N + n0 + tx * 4) = o;
    }
}

// ============================================================================
// Flash attention with relative-position bias + key padding mask.
// Block = 64 queries of one (b,h). 8 K/V tiles of 64 keys, online softmax.
// Smem: Qt (transposed), KP (K transposed, later aliased by P transposed),
//       Vs (row-major). 3 * 64*64 * 4B = 48KB exactly (static limit).
// ============================================================================
__global__ __launch_bounds__(256) void attn_kernel(
    const float* __restrict__ Q, const float* __restrict__ Kg,
    const float* __restrict__ Vg,
    const float* __restrict__ rel,           // [1023, 8]
    const unsigned int* __restrict__ kpm,    // [B, T], nonzero word => masked
    float* __restrict__ out)                 // [B, T, H, DK]
{
    __shared__ float Qt[64 * 64];   // Qt[d*64 + r]
    __shared__ float KP[64 * 64];   // Kt[d*64 + c]  then  Pt[k*64 + r]
    __shared__ float Vs[64 * 64];   // Vs[k*64 + d]

    const int bh = blockIdx.y;
    const int b  = bh >> 3;
    const int h  = bh & 7;
    const int q0 = blockIdx.x * 64;
    const int tid = threadIdx.x;
    const int ty = tid >> 4;       // row group
    const int tx = tid & 15;       // col group
    const int ldr = tid >> 4;      // loader: row base
    const int ldc = (tid & 15) * 4;

    // ---- load Q tile transposed ----
    {
        const float* qg = Q + ((size_t)(b * T_ + q0)) * D_ + h * DK_;
        #pragma unroll
        for (int rep = 0; rep < 4; rep++) {
            int r = ldr + rep * 16;
            float4 v = *(const float4*)(qg + (size_t)r * D_ + ldc);
            Qt[(ldc + 0) * 64 + r] = v.x;
            Qt[(ldc + 1) * 64 + r] = v.y;
            Qt[(ldc + 2) * 64 + r] = v.z;
            Qt[(ldc + 3) * 64 + r] = v.w;
        }
    }

    float m[4], l[4], o[4][4];
    #pragma unroll
    for (int i = 0; i < 4; i++) {
        m[i] = -1e30f; l[i] = 0.f;
        #pragma unroll
        for (int j = 0; j < 4; j++) o[i][j] = 0.f;
    }

    for (int kt = 0; kt < 8; kt++) {
        const int k0 = kt * 64;
        __syncthreads();   // prior PV reads of KP/Vs done (also covers Qt store on kt=0... see next sync)

        // ---- load K tile (transposed) and V tile ----
        const float* kg = Kg + ((size_t)(b * T_ + k0)) * D_ + h * DK_;
        const float* vg = Vg + ((size_t)(b * T_ + k0)) * D_ + h * DK_;
        #pragma unroll
        for (int rep = 0; rep < 4; rep++) {
            int r = ldr + rep * 16;
            float4 kv = *(const float4*)(kg + (size_t)r * D_ + ldc);
            KP[(ldc + 0) * 64 + r] = kv.x;
            KP[(ldc + 1) * 64 + r] = kv.y;
            KP[(ldc + 2) * 64 + r] = kv.z;
            KP[(ldc + 3) * 64 + r] = kv.w;
            float4 vv = *(const float4*)(vg + (size_t)r * D_ + ldc);
            *(float4*)&Vs[r * 64 + ldc] = vv;
        }
        __syncthreads();

        // ---- S = Q K^T ----
        float s[4][4] = {};
        #pragma unroll 16
        for (int d = 0; d < 64; d++) {
            float4 a4 = *(const float4*)&Qt[d * 64 + ty * 4];
            float4 b4 = *(const float4*)&KP[d * 64 + tx * 4];
            float a[4] = {a4.x, a4.y, a4.z, a4.w};
            float bb[4] = {b4.x, b4.y, b4.z, b4.w};
            #pragma unroll
            for (int i = 0; i < 4; i++)
                #pragma unroll
                for (int j = 0; j < 4; j++)
                    s[i][j] = fmaf(a[i], bb[j], s[i][j]);
        }
        __syncthreads();   // all threads done reading KP before Pt overwrite

        // ---- scale + rel-pos bias + mask ----
        // bias index: (k_abs - q_abs + 511)*8 + h ; distinct diffs j-i in [-3,3]
        const int base = (k0 + tx * 4 - q0 - ty * 4 + 511) * 8 + h;
        float r7[7];
        #pragma unroll
        for (int u = 0; u < 7; u++) r7[u] = __ldg(&rel[base + (u - 3) * 8]);
        float madd[4];
        #pragma unroll
        for (int j = 0; j < 4; j++)
            madd[j] = __ldg(&kpm[b * T_ + k0 + tx * 4 + j]) ? -2e30f : 0.f;

        #pragma unroll
        for (int i = 0; i < 4; i++)
            #pragma unroll
            for (int j = 0; j < 4; j++)
                s[i][j] = fmaf(s[i][j], 0.125f, r7[j - i + 3] + madd[j]);

        // ---- online softmax (row stats replicated over the 16 tx lanes) ----
        #pragma unroll
        for (int i = 0; i < 4; i++) {
            float rm = fmaxf(fmaxf(s[i][0], s[i][1]), fmaxf(s[i][2], s[i][3]));
            #pragma unroll
            for (int off = 8; off >= 1; off >>= 1)
                rm = fmaxf(rm, __shfl_xor_sync(0xffffffffu, rm, off));
            float mn = fmaxf(m[i], rm);
            float alpha = __expf(m[i] - mn);
            m[i] = mn;
            float rs = 0.f;
            #pragma unroll
            for (int j = 0; j < 4; j++) {
                float p = __expf(s[i][j] - mn);
                s[i][j] = p;
                rs += p;
            }
            #pragma unroll
            for (int off = 8; off >= 1; off >>= 1)
                rs += __shfl_xor_sync(0xffffffffu, rs, off);
            l[i] = l[i] * alpha + rs;
            #pragma unroll
            for (int j = 0; j < 4; j++) o[i][j] *= alpha;
        }

        // ---- write P transposed into KP ----
        #pragma unroll
        for (int i = 0; i < 4; i++)
            #pragma unroll
            for (int j = 0; j < 4; j++)
                KP[(tx * 4 + j) * 64 + (ty * 4 + i)] = s[i][j];
        __syncthreads();

        // ---- O += P V ----
        #pragma unroll 16
        for (int k = 0; k < 64; k++) {
            float4 a4 = *(const float4*)&KP[k * 64 + ty * 4];
            float4 b4 = *(const float4*)&Vs[k * 64 + tx * 4];
            float a[4] = {a4.x, a4.y, a4.z, a4.w};
            float bb[4] = {b4.x, b4.y, b4.z, b4.w};
            #pragma unroll
            for (int i = 0; i < 4; i++)
                #pragma unroll
                for (int j = 0; j < 4; j++)
                    o[i][j] = fmaf(a[i], bb[j], o[i][j]);
        }
    }

    // ---- epilogue: normalize and store ----
    #pragma unroll
    for (int i = 0; i < 4; i++) {
        float inv = 1.f / l[i];
        float4 ov;
        ov.x = o[i][0] * inv; ov.y = o[i][1] * inv;
        ov.z = o[i][2] * inv; ov.w = o[i][3] * inv;
        *(float4*)(out + ((size_t)(b * T_ + q0 + ty * 4 + i)) * D_ + h * DK_ + tx * 4) = ov;
    }
}

// ============================================================================
extern "C" void kernel_launch(void* const* d_in, const int* in_sizes, int n_in,
                              void* d_out, int out_size)
{
    const float* x   = (const float*)d_in[0];
    const float* Wq  = (const float*)d_in[1];
    const float* bq  = (const float*)d_in[2];
    const float* Wk  = (const float*)d_in[3];
    const float* bk  = (const float*)d_in[4];
    const float* Wv  = (const float*)d_in[5];
    const float* bv  = (const float*)d_in[6];
    const float* Wo  = (const float*)d_in[7];
    const float* bo  = (const float*)d_in[8];
    const float* rel = (const float*)d_in[9];
    const unsigned int* kpm = (const unsigned int*)d_in[10];
    float* out = (float*)d_out;

    float *qp, *kp, *vp, *ap;
    cudaGetSymbolAddress((void**)&qp, g_q);
    cudaGetSymbolAddress((void**)&kp, g_k);
    cudaGetSymbolAddress((void**)&vp, g_v);
    cudaGetSymbolAddress((void**)&ap, g_att);

    dim3 gemm_grid(D_ / 64, M_ / 64);   // (8, 256)
    sgemm_nt_bias<<<gemm_grid, 256>>>(x, Wq, bq, qp, M_, D_, D_);
    sgemm_nt_bias<<<gemm_grid, 256>>>(x, Wk, bk, kp, M_, D_, D_);
    sgemm_nt_bias<<<gemm_grid, 256>>>(x, Wv, bv, vp, M_, D_, D_);

    dim3 at_grid(T_ / 64, B_ * H_);     // (8, 256)
    attn_kernel<<<at_grid, 256>>>(qp, kp, vp, rel, kpm, ap);

    sgemm_nt_bias<<<gemm_grid, 256>>>(ap, Wo, bo, out, M_, D_, D_);
}